// round 14
// baseline (speedup 1.0000x reference)
#include <cuda_runtime.h>
#include <cuda_fp16.h>
#include <cstdint>

#define NROWS 8192
#define DDIM  256
#define NT    128                     // 64-row tiles per dimension
#define TS    64                      // tile size
#define NTILES (NT * (NT + 1) / 2)    // 8256 upper-triangle tile pairs
#define KCH   128                     // fp8 elems per k-chunk (128 B rows)
#define NCHUNK (DDIM / KCH)           // 2
#define HROWU4 (DDIM / 16)            // uint4 per 256-B fp8 row (16)
#define OFF_X1I 0
#define OFF_PI  8192
#define OFF_X1J 16384
#define OFF_PJ  24576
#define STAGE_BYTES 32768
#define DSMEM_BYTES (2 * STAGE_BYTES + 1024)

// Scratch (no allocations allowed)
__device__ float    g_n1sq[NROWS];
__device__ float    g_n2sq[NROWS];
__device__ float    g_npsq[NROWS];
__device__ uint32_t g_x1q[NROWS * DDIM / 4];   // e4m3 x1 (4 per word)
__device__ uint32_t g_pq [NROWS * DDIM / 4];   // e4m3 p  (4 per word)
__device__ double   g_acc;

// ---------------------------------------------------------------------------
// Helpers (generic sm_89+ PTX only — ptxas here targets plain sm_103)
// ---------------------------------------------------------------------------
__device__ __forceinline__ uint32_t smem_u32(const void* p) {
    uint32_t a;
    asm("{ .reg .u64 t; cvta.to.shared.u64 t, %1; cvt.u32.u64 %0, t; }"
        : "=r"(a) : "l"(p));
    return a;
}

// pack 4 floats -> 4 e4m3 bytes (x lowest byte .. w highest)
__device__ __forceinline__ uint32_t f4_to_e4m3x4(float x, float y, float z, float w) {
    uint16_t lo, hi;
    asm("cvt.rn.satfinite.e4m3x2.f32 %0, %1, %2;" : "=h"(lo) : "f"(y), "f"(x));
    asm("cvt.rn.satfinite.e4m3x2.f32 %0, %1, %2;" : "=h"(hi) : "f"(w), "f"(z));
    return (uint32_t)lo | ((uint32_t)hi << 16);
}

__device__ __forceinline__ void cp_async16(uint32_t smem_addr, const void* gptr) {
    asm volatile("cp.async.cg.shared.global [%0], [%1], 16;"
                 :: "r"(smem_addr), "l"(gptr) : "memory");
}
#define CP_COMMIT() asm volatile("cp.async.commit_group;" ::: "memory")
#define CP_WAIT(n)  asm volatile("cp.async.wait_group %0;" :: "n"(n) : "memory")

__device__ __forceinline__ void ldmx4(uint32_t* r, uint32_t addr) {
    asm volatile("ldmatrix.sync.aligned.m8n8.x4.shared.b16 {%0,%1,%2,%3}, [%4];"
                 : "=r"(r[0]), "=r"(r[1]), "=r"(r[2]), "=r"(r[3]) : "r"(addr));
}

// fp8 e4m3 MMA, fp32 accumulate: m16n8k32.row.col.
// Fragments match m16n8k16.f16 with 2 consecutive fp8 k-values per b16 slot,
// so the validated fp16 ldmatrix geometry carries over unchanged.
__device__ __forceinline__ void mma_e4m3(float* d, const uint32_t* a,
                                         const uint32_t* b) {
    asm volatile(
        "mma.sync.aligned.m16n8k32.row.col.f32.e4m3.e4m3.f32 "
        "{%0,%1,%2,%3}, {%4,%5,%6,%7}, {%8,%9}, {%0,%1,%2,%3};"
        : "+f"(d[0]), "+f"(d[1]), "+f"(d[2]), "+f"(d[3])
        : "r"(a[0]), "r"(a[1]), "r"(a[2]), "r"(a[3]), "r"(b[0]), "r"(b[1]));
}

// ---------------------------------------------------------------------------
__global__ void mqjs_init_kernel() { g_acc = 0.0; }

// Prep: per-row norms (fp32, exact) + e4m3 conversions of x1 and p=(x1+x2)/2.
// One warp per row.
__global__ void mqjs_prep_kernel(const float* __restrict__ x1,
                                 const float* __restrict__ x2) {
    int warp = threadIdx.x >> 5;
    int lane = threadIdx.x & 31;
    int row  = blockIdx.x * 8 + warp;

    const float4* p1 = reinterpret_cast<const float4*>(x1 + (size_t)row * DDIM);
    const float4* p2 = reinterpret_cast<const float4*>(x2 + (size_t)row * DDIM);
    uint32_t* o1 = g_x1q + (size_t)row * (DDIM / 4);
    uint32_t* op = g_pq  + (size_t)row * (DDIM / 4);

    float s1 = 0.f, s2 = 0.f, sp = 0.f;
#pragma unroll
    for (int it = 0; it < 2; it++) {
        int pos = lane + it * 32;
        float4 a = p1[pos];
        float4 b = p2[pos];
        s1 += a.x * a.x + a.y * a.y + a.z * a.z + a.w * a.w;
        s2 += b.x * b.x + b.y * b.y + b.z * b.z + b.w * b.w;
        float px = 0.5f * (a.x + b.x), py = 0.5f * (a.y + b.y);
        float pz = 0.5f * (a.z + b.z), pw = 0.5f * (a.w + b.w);
        sp += px * px + py * py + pz * pz + pw * pw;
        o1[pos] = f4_to_e4m3x4(a.x, a.y, a.z, a.w);
        op[pos] = f4_to_e4m3x4(px, py, pz, pw);
    }
#pragma unroll
    for (int off = 16; off > 0; off >>= 1) {
        s1 += __shfl_xor_sync(0xFFFFFFFFu, s1, off);
        s2 += __shfl_xor_sync(0xFFFFFFFFu, s2, off);
        sp += __shfl_xor_sync(0xFFFFFFFFu, sp, off);
    }
    if (lane == 0) { g_n1sq[row] = s1; g_n2sq[row] = s2; g_npsq[row] = sp; }
}

// ---------------------------------------------------------------------------
// Triangular-tile fused quad-Gram (e4m3 mma.sync, fp32 accum):
//   S = X1_i.P_j^T, T = P_i.X1_j^T, G = P_i.P_j^T, D3 = X1_i.X1_j^T
//   d1_ij = n1i+npj-2S, d2_ij = n2i+npj-2(2G-S)
//   d1_ji = n1j+npi-2T, d2_ji = n2j+npi-2(2G-T)
//   d3    = n1i+n1j-2D3 (weight 2 off-diag tiles, 1 on diag; i==j forced 0 —
//   true dist is exactly 0 -> reference log term is 0; fp8 noise (+-~2) would
//   otherwise leak past the max(d,1) clamp)
// CTA tile 64x64; 8 warps as 2(m)x4(n); warp tile 32(m)x16(n).
// Producers: cp.async from pre-converted fp8 globals; double-buffered; the
// 128-B-row swizzle/ldmatrix geometry is identical to the fp16 version.
// ---------------------------------------------------------------------------
__global__ __launch_bounds__(256, 2)
void mqjs_mma_kernel() {
    extern __shared__ char dsm[];
    __shared__ float s_nrm[6][TS];   // n1/n2/np @ib, n1/n2/np @jb
    __shared__ float s_red[8];

    const int tid  = threadIdx.x;
    const int lane = tid & 31;
    const int wid  = tid >> 5;
    const int wm   = wid & 1;
    const int wn   = wid >> 1;
    const int mb_w = wm * 32;
    const int nb_w = wn * 16;

    // ---- triangle decode: blockIdx.x -> (bi, bj), bi <= bj ----
    int t = blockIdx.x;
    int bi = (int)((2.f * NT + 1.f
                    - sqrtf((2.f * NT + 1.f) * (2.f * NT + 1.f) - 8.f * t)) * 0.5f);
    while ((bi + 1) * NT - ((bi + 1) * bi) / 2 <= t) bi++;
    while (bi * NT - (bi * (bi - 1)) / 2 > t) bi--;
    const int bj = bi + (t - (bi * NT - (bi * (bi - 1)) / 2));
    const int ib = bi * TS;
    const int jb = bj * TS;

    const uint32_t su = (smem_u32(dsm) + 1023u) & ~1023u;

    if (tid < TS) {
        s_nrm[0][tid] = g_n1sq[ib + tid];
        s_nrm[1][tid] = g_n2sq[ib + tid];
        s_nrm[2][tid] = g_npsq[ib + tid];
        s_nrm[3][tid] = g_n1sq[jb + tid];
        s_nrm[4][tid] = g_n2sq[jb + tid];
        s_nrm[5][tid] = g_npsq[jb + tid];
    }

    const uint4* x1i = reinterpret_cast<const uint4*>(g_x1q) + (size_t)ib * HROWU4;
    const uint4* pi  = reinterpret_cast<const uint4*>(g_pq)  + (size_t)ib * HROWU4;
    const uint4* x1j = reinterpret_cast<const uint4*>(g_x1q) + (size_t)jb * HROWU4;
    const uint4* pj  = reinterpret_cast<const uint4*>(g_pq)  + (size_t)jb * HROWU4;

    // per-thread cp.async geometry (2 reps x 4 tiles = 8 per chunk)
    const int r0 = tid >> 3,         c0 = tid & 7;
    const int r1 = (tid + 256) >> 3, c1 = (tid + 256) & 7;
    const uint32_t d0 = (uint32_t)(r0 * 128 + ((c0 ^ (r0 & 7)) << 4));
    const uint32_t d1 = (uint32_t)(r1 * 128 + ((c1 ^ (r1 & 7)) << 4));

#define ISSUE_CHUNK(cc, sb_)                                                   \
    {                                                                          \
        int g0 = r0 * HROWU4 + (cc) * 8 + c0;                                  \
        int g1 = r1 * HROWU4 + (cc) * 8 + c1;                                  \
        cp_async16((sb_) + OFF_X1I + d0, x1i + g0);                            \
        cp_async16((sb_) + OFF_PI  + d0, pi  + g0);                            \
        cp_async16((sb_) + OFF_X1J + d0, x1j + g0);                            \
        cp_async16((sb_) + OFF_PJ  + d0, pj  + g0);                            \
        cp_async16((sb_) + OFF_X1I + d1, x1i + g1);                            \
        cp_async16((sb_) + OFF_PI  + d1, pi  + g1);                            \
        cp_async16((sb_) + OFF_X1J + d1, x1j + g1);                            \
        cp_async16((sb_) + OFF_PJ  + d1, pj  + g1);                            \
        CP_COMMIT();                                                           \
    }

    // ldmatrix per-lane constants (32-byte k-step; identical to fp16 version)
    const int arow = (lane & 7) | (((lane >> 3) & 1) << 3);
    const uint32_t ahi  = (uint32_t)(((lane >> 4) & 1) << 4);
    const uint32_t aswz = (uint32_t)((arow & 7) << 4);
    const uint32_t aRow0 = (uint32_t)((mb_w + arow) * 128);
    const int brow = (lane & 7) | (((lane >> 4) & 1) << 3);
    const uint32_t bhi  = (uint32_t)(((lane >> 3) & 1) << 4);
    const uint32_t bswz = (uint32_t)((brow & 7) << 4);
    const uint32_t bRow0 = (uint32_t)((nb_w + brow) * 128);

    float aS[2][2][4], aT[2][2][4], aG[2][2][4], aD[2][2][4];
#pragma unroll
    for (int mt = 0; mt < 2; mt++)
#pragma unroll
        for (int n8 = 0; n8 < 2; n8++)
#pragma unroll
            for (int e = 0; e < 4; e++) {
                aS[mt][n8][e] = 0.f; aT[mt][n8][e] = 0.f;
                aG[mt][n8][e] = 0.f; aD[mt][n8][e] = 0.f;
            }

    // issue both chunks up front (two commit groups), then compute each
    ISSUE_CHUNK(0, su);
    ISSUE_CHUNK(1, su + STAGE_BYTES);

#pragma unroll
    for (int c = 0; c < NCHUNK; c++) {
        const uint32_t sb = su + (uint32_t)c * STAGE_BYTES;
        if (c == 0) { CP_WAIT(1); } else { CP_WAIT(0); }
        __syncthreads();

#pragma unroll
        for (int ks = 0; ks < 4; ks++) {     // K=32 fp8 per step, 4 steps/chunk
            const uint32_t ak = ((uint32_t)(ks * 32) + ahi) ^ aswz;
            const uint32_t bk = ((uint32_t)(ks * 32) + bhi) ^ bswz;
            uint32_t fa1[8], fap[8], fb1[4], fbp[4];
            ldmx4(fa1 + 0, sb + OFF_X1I + aRow0 + ak);
            ldmx4(fa1 + 4, sb + OFF_X1I + aRow0 + 2048 + ak);
            ldmx4(fap + 0, sb + OFF_PI  + aRow0 + ak);
            ldmx4(fap + 4, sb + OFF_PI  + aRow0 + 2048 + ak);
            ldmx4(fb1,     sb + OFF_X1J + bRow0 + bk);
            ldmx4(fbp,     sb + OFF_PJ  + bRow0 + bk);
#pragma unroll
            for (int mt = 0; mt < 2; mt++) {
#pragma unroll
                for (int n8 = 0; n8 < 2; n8++) {
                    mma_e4m3(aS[mt][n8], fa1 + mt * 4, fbp + n8 * 2);
                    mma_e4m3(aT[mt][n8], fap + mt * 4, fb1 + n8 * 2);
                    mma_e4m3(aG[mt][n8], fap + mt * 4, fbp + n8 * 2);
                    mma_e4m3(aD[mt][n8], fa1 + mt * 4, fb1 + n8 * 2);
                }
            }
        }
    }

    // ---- epilogue ----
    const float cse = (float)NROWS / (float)(NROWS - 1);
    const bool  diag = (bi == bj);
    const float wT  = diag ? 0.f : 1.f;
    const float w3c = (diag ? 1.f : 2.f) * cse * 0.5f;
    const int rbase = mb_w + (lane >> 2);
    const int cbase = nb_w + (lane & 3) * 2;

    float part = 0.f;
#pragma unroll
    for (int mt = 0; mt < 2; mt++) {
        const int rA = rbase + mt * 16;
        const int rB = rA + 8;
        const float n1iA = s_nrm[0][rA], n2iA = s_nrm[1][rA], npiA = s_nrm[2][rA];
        const float n1iB = s_nrm[0][rB], n2iB = s_nrm[1][rB], npiB = s_nrm[2][rB];
#pragma unroll
        for (int n8 = 0; n8 < 2; n8++) {
            const int cA = cbase + n8 * 8;
            const int cB = cA + 1;
            const float n1jA = s_nrm[3][cA], n2jA = s_nrm[4][cA], npjA = s_nrm[5][cA];
            const float n1jB = s_nrm[3][cB], n2jB = s_nrm[4][cB], npjB = s_nrm[5][cB];
            const float* S = aS[mt][n8];
            const float* T = aT[mt][n8];
            const float* G = aG[mt][n8];
            const float* D = aD[mt][n8];
#pragma unroll
            for (int e = 0; e < 4; e++) {
                const int   rr  = (e < 2) ? rA : rB;
                const int   cc_ = (e & 1) ? cB : cA;
                const float n1i = (e < 2) ? n1iA : n1iB;
                const float n2i = (e < 2) ? n2iA : n2iB;
                const float npi = (e < 2) ? npiA : npiB;
                const float n1j = (e & 1) ? n1jB : n1jA;
                const float n2j = (e & 1) ? n2jB : n2jA;
                const float npj = (e & 1) ? npjB : npjA;
                const float s = S[e], tt = T[e], g2 = 2.f * G[e], dd = D[e];
                const float w3e = (diag && rr == cc_) ? 0.f : w3c;
                float d1a = n1i + npj - 2.f * s;
                float d2a = n2i + npj - 2.f * (g2 - s);
                float d1b = n1j + npi - 2.f * tt;
                float d2b = n2j + npi - 2.f * (g2 - tt);
                float d3  = n1i + n1j - 2.f * dd;
                part += 0.5f * (__logf(fmaxf(d1a, 1.f)) + __logf(fmaxf(d2a, 1.f)));
                part += wT * 0.5f * (__logf(fmaxf(d1b, 1.f)) + __logf(fmaxf(d2b, 1.f)));
                part -= w3e * __logf(fmaxf(d3, 1.f));
            }
        }
    }

    // ---- reduction ----
#pragma unroll
    for (int off = 16; off > 0; off >>= 1)
        part += __shfl_xor_sync(0xFFFFFFFFu, part, off);
    if (lane == 0) s_red[wid] = part;
    __syncthreads();
    if (tid == 0) {
        float tot = 0.f;
#pragma unroll
        for (int w = 0; w < 8; w++) tot += s_red[w];
        atomicAdd(&g_acc, (double)tot);
    }
}

// ---------------------------------------------------------------------------
__global__ void mqjs_finalize_kernel(float* out) {
    out[0] = (float)(g_acc / (double)NROWS);
}

// ---------------------------------------------------------------------------
extern "C" void kernel_launch(void* const* d_in, const int* in_sizes, int n_in,
                              void* d_out, int out_size) {
    const float* x1 = (const float*)d_in[0];   // input
    const float* x2 = (const float*)d_in[1];   // target
    float* out = (float*)d_out;

    cudaFuncSetAttribute(mqjs_mma_kernel,
                         cudaFuncAttributeMaxDynamicSharedMemorySize, DSMEM_BYTES);

    mqjs_init_kernel<<<1, 1>>>();
    mqjs_prep_kernel<<<NROWS / 8, 256>>>(x1, x2);
    mqjs_mma_kernel<<<NTILES, 256, DSMEM_BYTES>>>();
    mqjs_finalize_kernel<<<1, 1>>>(out);
}

// round 17
// speedup vs baseline: 1.1328x; 1.1328x over previous
#include <cuda_runtime.h>
#include <cuda_fp16.h>
#include <cstdint>

#define NROWS 8192
#define DDIM  256
#define NT    128                     // 64-row tiles per dimension
#define TS    64                      // tile size
#define NTILES (NT * (NT + 1) / 2)    // 8256 upper-triangle tile pairs
#define NCHUNK 4                      // K chunks of 64 halfs (128 B rows)
#define HROW4 (DDIM / 8)              // uint4 per fp16 row (32)
#define OFF_X1I 0
#define OFF_PI  8192
#define OFF_X1J 16384
#define OFF_PJ  24576
#define STAGE_BYTES 32768
#define NSTAGE 3
#define DSMEM_BYTES (NSTAGE * STAGE_BYTES + 1024)
#define GRID_MAIN 296                 // 2 persistent CTAs per SM

// Scratch (no allocations allowed)
__device__ float    g_n1sq[NROWS];
__device__ float    g_n2sq[NROWS];
__device__ float    g_npsq[NROWS];
__device__ uint32_t g_x1h[NROWS * DDIM / 2];   // fp16 x1 (packed half2)
__device__ uint32_t g_ph [NROWS * DDIM / 2];   // fp16 p  (packed half2)
__device__ double   g_acc;

// ---------------------------------------------------------------------------
// Helpers (generic sm_80+ PTX only — ptxas here targets plain sm_103)
// ---------------------------------------------------------------------------
__device__ __forceinline__ uint32_t smem_u32(const void* p) {
    uint32_t a;
    asm("{ .reg .u64 t; cvta.to.shared.u64 t, %1; cvt.u32.u64 %0, t; }"
        : "=r"(a) : "l"(p));
    return a;
}

__device__ __forceinline__ void cp_async16(uint32_t smem_addr, const void* gptr) {
    asm volatile("cp.async.cg.shared.global [%0], [%1], 16;"
                 :: "r"(smem_addr), "l"(gptr) : "memory");
}
#define CP_COMMIT() asm volatile("cp.async.commit_group;" ::: "memory")
#define CP_WAIT(n)  asm volatile("cp.async.wait_group %0;" :: "n"(n) : "memory")

__device__ __forceinline__ void ldmx4(uint32_t* r, uint32_t addr) {
    asm volatile("ldmatrix.sync.aligned.m8n8.x4.shared.b16 {%0,%1,%2,%3}, [%4];"
                 : "=r"(r[0]), "=r"(r[1]), "=r"(r[2]), "=r"(r[3]) : "r"(addr));
}

// fp16 MMA, fp32 accumulate: m16n8k16.row.col
__device__ __forceinline__ void mma_f16(float* d, const uint32_t* a,
                                        const uint32_t* b) {
    asm volatile(
        "mma.sync.aligned.m16n8k16.row.col.f32.f16.f16.f32 "
        "{%0,%1,%2,%3}, {%4,%5,%6,%7}, {%8,%9}, {%0,%1,%2,%3};"
        : "+f"(d[0]), "+f"(d[1]), "+f"(d[2]), "+f"(d[3])
        : "r"(a[0]), "r"(a[1]), "r"(a[2]), "r"(a[3]), "r"(b[0]), "r"(b[1]));
}

// triangle decode: t -> (bi, bj), bi <= bj
__device__ __forceinline__ void tile_decode(int t, int& bi_, int& bj_) {
    int b = (int)((2.f * NT + 1.f
                   - sqrtf((2.f * NT + 1.f) * (2.f * NT + 1.f) - 8.f * t)) * 0.5f);
    while ((b + 1) * NT - ((b + 1) * b) / 2 <= t) b++;
    while (b * NT - (b * (b - 1)) / 2 > t) b--;
    bi_ = b;
    bj_ = b + (t - (b * NT - (b * (b - 1)) / 2));
}

// ---------------------------------------------------------------------------
__global__ void mqjs_init_kernel() { g_acc = 0.0; }

// Prep: per-row norms (fp32, exact) + fp16 conversions of x1 and p=(x1+x2)/2.
__global__ void mqjs_prep_kernel(const float* __restrict__ x1,
                                 const float* __restrict__ x2) {
    int warp = threadIdx.x >> 5;
    int lane = threadIdx.x & 31;
    int row  = blockIdx.x * 8 + warp;

    const float4* p1 = reinterpret_cast<const float4*>(x1 + (size_t)row * DDIM);
    const float4* p2 = reinterpret_cast<const float4*>(x2 + (size_t)row * DDIM);
    uint2* o1 = reinterpret_cast<uint2*>(g_x1h + (size_t)row * (DDIM / 2));
    uint2* op = reinterpret_cast<uint2*>(g_ph  + (size_t)row * (DDIM / 2));

    float s1 = 0.f, s2 = 0.f, sp = 0.f;
#pragma unroll
    for (int it = 0; it < 2; it++) {
        int pos = lane + it * 32;
        float4 a = p1[pos];
        float4 b = p2[pos];
        s1 += a.x * a.x + a.y * a.y + a.z * a.z + a.w * a.w;
        s2 += b.x * b.x + b.y * b.y + b.z * b.z + b.w * b.w;
        float px = 0.5f * (a.x + b.x), py = 0.5f * (a.y + b.y);
        float pz = 0.5f * (a.z + b.z), pw = 0.5f * (a.w + b.w);
        sp += px * px + py * py + pz * pz + pw * pw;
        __half2 axy = __floats2half2_rn(a.x, a.y);
        __half2 azw = __floats2half2_rn(a.z, a.w);
        __half2 pxy = __floats2half2_rn(px, py);
        __half2 pzw = __floats2half2_rn(pz, pw);
        uint2 ua, up;
        ua.x = *reinterpret_cast<uint32_t*>(&axy);
        ua.y = *reinterpret_cast<uint32_t*>(&azw);
        up.x = *reinterpret_cast<uint32_t*>(&pxy);
        up.y = *reinterpret_cast<uint32_t*>(&pzw);
        o1[pos] = ua;
        op[pos] = up;
    }
#pragma unroll
    for (int off = 16; off > 0; off >>= 1) {
        s1 += __shfl_xor_sync(0xFFFFFFFFu, s1, off);
        s2 += __shfl_xor_sync(0xFFFFFFFFu, s2, off);
        sp += __shfl_xor_sync(0xFFFFFFFFu, sp, off);
    }
    if (lane == 0) { g_n1sq[row] = s1; g_n2sq[row] = s2; g_npsq[row] = sp; }
}

// ---------------------------------------------------------------------------
// Persistent-CTA fused quad-Gram (fp16 mma.sync, fp32 accum):
//   S = X1_i.P_j^T, T = P_i.X1_j^T, G = P_i.P_j^T, D3 = X1_i.X1_j^T
// 296 persistent CTAs loop over triangle tiles; a 3-stage cp.async ring flows
// continuously across tile boundaries. Race-free stage reuse: each chunk
// iteration is WAIT -> syncthreads -> ISSUE(next) -> COMPUTE(cur), so the
// issue into a stage is separated from all reads of that stage by a barrier.
// CTA tile 64x64; 8 warps as 2(m)x4(n); warp tile 32(m)x16(n).
// ---------------------------------------------------------------------------
__global__ __launch_bounds__(256, 2)
void mqjs_mma_kernel() {
    extern __shared__ char dsm[];
    __shared__ float s_nrm[2][6][TS];   // double-buffered per-tile norms
    __shared__ float s_red[8];

    const int tid  = threadIdx.x;
    const int lane = tid & 31;
    const int wid  = tid >> 5;
    const int wm   = wid & 1;
    const int wn   = wid >> 1;
    const int mb_w = wm * 32;
    const int nb_w = wn * 16;

    const uint32_t su    = (smem_u32(dsm) + 1023u) & ~1023u;
    const uint32_t suTop = su + (NSTAGE - 1) * STAGE_BYTES;

    const uint4* bx1 = reinterpret_cast<const uint4*>(g_x1h);
    const uint4* bph = reinterpret_cast<const uint4*>(g_ph);

    // per-thread cp.async geometry (2 reps x 4 tiles = 8 per chunk)
    const int r0 = tid >> 3,         c0 = tid & 7;
    const int r1 = (tid + 256) >> 3, c1 = (tid + 256) & 7;
    const uint32_t d0 = (uint32_t)(r0 * 128 + ((c0 ^ (r0 & 7)) << 4));
    const uint32_t d1 = (uint32_t)(r1 * 128 + ((c1 ^ (r1 & 7)) << 4));

#define ISSUE_CHUNK(iOff, jOff, cc, sb_)                                       \
    {                                                                          \
        int g0 = r0 * HROW4 + (cc) * 8 + c0;                                   \
        int g1 = r1 * HROW4 + (cc) * 8 + c1;                                   \
        cp_async16((sb_) + OFF_X1I + d0, bx1 + (iOff) + g0);                   \
        cp_async16((sb_) + OFF_PI  + d0, bph + (iOff) + g0);                   \
        cp_async16((sb_) + OFF_X1J + d0, bx1 + (jOff) + g0);                   \
        cp_async16((sb_) + OFF_PJ  + d0, bph + (jOff) + g0);                   \
        cp_async16((sb_) + OFF_X1I + d1, bx1 + (iOff) + g1);                   \
        cp_async16((sb_) + OFF_PI  + d1, bph + (iOff) + g1);                   \
        cp_async16((sb_) + OFF_X1J + d1, bx1 + (jOff) + g1);                   \
        cp_async16((sb_) + OFF_PJ  + d1, bph + (jOff) + g1);                   \
        CP_COMMIT();                                                           \
    }
#define RING_ADV(v) (v) = ((v) == suTop) ? su : (v) + STAGE_BYTES

    // ldmatrix per-lane constants (32-byte k-step)
    const int arow = (lane & 7) | (((lane >> 3) & 1) << 3);
    const uint32_t ahi  = (uint32_t)(((lane >> 4) & 1) << 4);
    const uint32_t aswz = (uint32_t)((arow & 7) << 4);
    const uint32_t aRow0 = (uint32_t)((mb_w + arow) * 128);
    const int brow = (lane & 7) | (((lane >> 4) & 1) << 3);
    const uint32_t bhi  = (uint32_t)(((lane >> 3) & 1) << 4);
    const uint32_t bswz = (uint32_t)((brow & 7) << 4);
    const uint32_t bRow0 = (uint32_t)((nb_w + brow) * 128);

    float aS[2][2][4], aT[2][2][4], aG[2][2][4], aD[2][2][4];

#define COMPUTE_CHUNK(sb_)                                                     \
    {                                                                          \
        _Pragma("unroll")                                                      \
        for (int ks = 0; ks < 4; ks++) {                                       \
            const uint32_t ak = ((uint32_t)(ks * 32) + ahi) ^ aswz;            \
            const uint32_t bk = ((uint32_t)(ks * 32) + bhi) ^ bswz;            \
            uint32_t fa1[8], fap[8], fb1[4], fbp[4];                           \
            ldmx4(fa1 + 0, (sb_) + OFF_X1I + aRow0 + ak);                      \
            ldmx4(fa1 + 4, (sb_) + OFF_X1I + aRow0 + 2048 + ak);               \
            ldmx4(fap + 0, (sb_) + OFF_PI  + aRow0 + ak);                      \
            ldmx4(fap + 4, (sb_) + OFF_PI  + aRow0 + 2048 + ak);               \
            ldmx4(fb1,     (sb_) + OFF_X1J + bRow0 + bk);                      \
            ldmx4(fbp,     (sb_) + OFF_PJ  + bRow0 + bk);                      \
            _Pragma("unroll")                                                  \
            for (int mt = 0; mt < 2; mt++) {                                   \
                _Pragma("unroll")                                              \
                for (int n8 = 0; n8 < 2; n8++) {                               \
                    mma_f16(aS[mt][n8], fa1 + mt * 4, fbp + n8 * 2);           \
                    mma_f16(aT[mt][n8], fap + mt * 4, fb1 + n8 * 2);           \
                    mma_f16(aG[mt][n8], fap + mt * 4, fbp + n8 * 2);           \
                    mma_f16(aD[mt][n8], fa1 + mt * 4, fb1 + n8 * 2);           \
                }                                                              \
            }                                                                  \
        }                                                                      \
    }

    const float cse = (float)NROWS / (float)(NROWS - 1);
    const int rbase = mb_w + (lane >> 2);
    const int cbase = nb_w + (lane & 3) * 2;

    // ---- persistent tile loop with continuous 3-stage ring ----
    uint32_t sIss = su, sCmp = su;
    int t = blockIdx.x;
    int bi, bj;
    tile_decode(t, bi, bj);
    int iOff = bi * TS * HROW4;
    int jOff = bj * TS * HROW4;

    ISSUE_CHUNK(iOff, jOff, 0, sIss); RING_ADV(sIss);
    ISSUE_CHUNK(iOff, jOff, 1, sIss); RING_ADV(sIss);

    float part = 0.f;
    int buf = 0;

    for (;;) {
        const int tn = t + GRID_MAIN;
        const bool hn = (tn < NTILES);
        int nbi = 0, nbj = 0, niOff = 0, njOff = 0;
        if (hn) {
            tile_decode(tn, nbi, nbj);
            niOff = nbi * TS * HROW4;
            njOff = nbj * TS * HROW4;
        }
        // per-tile norms (double-buffered; barriers below gate reuse)
        if (tid < TS) {
            const int ib = bi * TS, jb = bj * TS;
            s_nrm[buf][0][tid] = g_n1sq[ib + tid];
            s_nrm[buf][1][tid] = g_n2sq[ib + tid];
            s_nrm[buf][2][tid] = g_npsq[ib + tid];
            s_nrm[buf][3][tid] = g_n1sq[jb + tid];
            s_nrm[buf][4][tid] = g_n2sq[jb + tid];
            s_nrm[buf][5][tid] = g_npsq[jb + tid];
        }
#pragma unroll
        for (int mt = 0; mt < 2; mt++)
#pragma unroll
            for (int n8 = 0; n8 < 2; n8++)
#pragma unroll
                for (int e = 0; e < 4; e++) {
                    aS[mt][n8][e] = 0.f; aT[mt][n8][e] = 0.f;
                    aG[mt][n8][e] = 0.f; aD[mt][n8][e] = 0.f;
                }

        // Each chunk: WAIT -> sync -> ISSUE(next, into stage all threads have
        // finished reading, guaranteed by the sync) -> COMPUTE(cur).
        // c=0
        CP_WAIT(1); __syncthreads();
        ISSUE_CHUNK(iOff, jOff, 2, sIss); RING_ADV(sIss);
        COMPUTE_CHUNK(sCmp); RING_ADV(sCmp);
        // c=1
        CP_WAIT(1); __syncthreads();
        ISSUE_CHUNK(iOff, jOff, 3, sIss); RING_ADV(sIss);
        COMPUTE_CHUNK(sCmp); RING_ADV(sCmp);
        // c=2 (start next tile's stream)
        CP_WAIT(1); __syncthreads();
        if (hn) { ISSUE_CHUNK(niOff, njOff, 0, sIss); RING_ADV(sIss); }
        COMPUTE_CHUNK(sCmp); RING_ADV(sCmp);
        // c=3
        if (hn) { CP_WAIT(1); } else { CP_WAIT(0); }
        __syncthreads();
        if (hn) { ISSUE_CHUNK(niOff, njOff, 1, sIss); RING_ADV(sIss); }
        COMPUTE_CHUNK(sCmp); RING_ADV(sCmp);

        // ---- epilogue (overlaps next tile's in-flight cp.async) ----
        {
            const bool  diag = (bi == bj);
            const float wTt = diag ? 0.f : 1.f;
            const float w3c = (diag ? 1.f : 2.f) * cse;
#pragma unroll
            for (int mt = 0; mt < 2; mt++) {
                const int rA = rbase + mt * 16;
                const int rB = rA + 8;
                const float n1iA = s_nrm[buf][0][rA], n2iA = s_nrm[buf][1][rA];
                const float npiA = s_nrm[buf][2][rA];
                const float n1iB = s_nrm[buf][0][rB], n2iB = s_nrm[buf][1][rB];
                const float npiB = s_nrm[buf][2][rB];
#pragma unroll
                for (int n8 = 0; n8 < 2; n8++) {
                    const int cA = cbase + n8 * 8;
                    const int cB = cA + 1;
                    const float n1jA = s_nrm[buf][3][cA], n2jA = s_nrm[buf][4][cA];
                    const float npjA = s_nrm[buf][5][cA];
                    const float n1jB = s_nrm[buf][3][cB], n2jB = s_nrm[buf][4][cB];
                    const float npjB = s_nrm[buf][5][cB];
                    const float* S = aS[mt][n8];
                    const float* T = aT[mt][n8];
                    const float* G = aG[mt][n8];
                    const float* D = aD[mt][n8];
                    float p1 = 1.f, p2 = 1.f, p3 = 1.f;
#pragma unroll
                    for (int e = 0; e < 4; e++) {
                        const int   rr  = (e < 2) ? rA : rB;
                        const int   cc_ = (e & 1) ? cB : cA;
                        const float n1i = (e < 2) ? n1iA : n1iB;
                        const float n2i = (e < 2) ? n2iA : n2iB;
                        const float npi = (e < 2) ? npiA : npiB;
                        const float n1j = (e & 1) ? n1jB : n1jA;
                        const float n2j = (e & 1) ? n2jB : n2jA;
                        const float npj = (e & 1) ? npjB : npjA;
                        const float s = S[e], tt = T[e], g2 = 2.f * G[e], dd = D[e];
                        float d1a = fmaxf(n1i + npj - 2.f * s, 1.f);
                        float d2a = fmaxf(n2i + npj - 2.f * (g2 - s), 1.f);
                        float d1b = fmaxf(n1j + npi - 2.f * tt, 1.f);
                        float d2b = fmaxf(n2j + npi - 2.f * (g2 - tt), 1.f);
                        float d3  = (diag && rr == cc_)
                                        ? 1.f : fmaxf(n1i + n1j - 2.f * dd, 1.f);
                        p1 *= d1a * d2a;     // <= ~(7e2)^8 = 6e22, fp32-safe
                        p2 *= d1b * d2b;
                        p3 *= d3;            // <= ~(2e3)^4 = 1.6e13
                    }
                    part += 0.5f * (__logf(p1) + wTt * __logf(p2))
                          - 0.5f * w3c * __logf(p3);
                }
            }
        }

        if (!hn) break;
        t = tn; bi = nbi; bj = nbj; iOff = niOff; jOff = njOff; buf ^= 1;
    }

    // ---- one reduction per CTA ----
#pragma unroll
    for (int off = 16; off > 0; off >>= 1)
        part += __shfl_xor_sync(0xFFFFFFFFu, part, off);
    if (lane == 0) s_red[wid] = part;
    __syncthreads();
    if (tid == 0) {
        float tot = 0.f;
#pragma unroll
        for (int w = 0; w < 8; w++) tot += s_red[w];
        atomicAdd(&g_acc, (double)tot);
    }
}

// ---------------------------------------------------------------------------
__global__ void mqjs_finalize_kernel(float* out) {
    out[0] = (float)(g_acc / (double)NROWS);
}

// ---------------------------------------------------------------------------
extern "C" void kernel_launch(void* const* d_in, const int* in_sizes, int n_in,
                              void* d_out, int out_size) {
    const float* x1 = (const float*)d_in[0];   // input
    const float* x2 = (const float*)d_in[1];   // target
    float* out = (float*)d_out;

    cudaFuncSetAttribute(mqjs_mma_kernel,
                         cudaFuncAttributeMaxDynamicSharedMemorySize, DSMEM_BYTES);

    mqjs_init_kernel<<<1, 1>>>();
    mqjs_prep_kernel<<<NROWS / 8, 256>>>(x1, x2);
    mqjs_mma_kernel<<<GRID_MAIN, 256, DSMEM_BYTES>>>();
    mqjs_finalize_kernel<<<1, 1>>>(out);
}